// round 1
// baseline (speedup 1.0000x reference)
#include <cuda_runtime.h>

// WLC loss, fused 5-iteration morphological recurrence, single pass over HBM.
// Tile 128x128, halo 5 -> extended 138x138 in SMEM. Ping-pong pred buffers +
// gt buffer, all fp32, ~231.9 KB dynamic SMEM, 1 CTA/SM.

#define IMG    4096
#define TS     128
#define HLO    5
#define EXT    138            // TS + 2*HLO
#define STRIDE 140            // padded row (floats), 16B-aligned rows
#define BUF    (EXT * STRIDE) // 19320 floats per buffer
#define NT     512
#define NQ     35             // float4 quad-columns covering cols 0..139
#define STRIPS 14             // row strips per quad column
#define RPS    10             // rows per strip (covers rows 1..136)
#define CLO    HLO            // central region [5,133)
#define CHI    (HLO + TS)

__device__ float g_acc[2];    // [0] = sum_k w_k * S_k, [1] = gt_sum

__global__ void wlc_zero() { g_acc[0] = 0.0f; g_acc[1] = 0.0f; }

__device__ __forceinline__ float sigm(float x) {
    // 1 / (1 + e^{-x});  EX2 + RCP (2 MUFU). Saturates correctly at +/-inf.
    return __fdividef(1.0f, 1.0f + __expf(-x));
}

// Load one row's center float4 + horizontal 3-sums for a quad column.
__device__ __forceinline__ void load_row(const float* __restrict__ S, int idx,
                                         float4& c, float4& h) {
    c = *reinterpret_cast<const float4*>(S + idx);
    float l = S[idx - 1];
    float r = S[idx + 4];
    h.x = l   + c.x + c.y;
    h.y = c.x + c.y + c.z;
    h.z = c.y + c.z + c.w;
    h.w = c.z + c.w + r;
}

__global__ __launch_bounds__(NT, 1)
void wlc_main(const float* __restrict__ pred, const float* __restrict__ gt)
{
    extern __shared__ float sm[];
    float* Gs = sm;               // gt tile        (BUF floats)
    float* A0 = sm + BUF;         // pred ping      (BUF floats)
    float* A1 = sm + 2 * BUF;     // pred pong      (BUF floats) + 64B slack

    const int tid = threadIdx.x;
    const int gx0 = blockIdx.x * TS - HLO;
    const int gy0 = blockIdx.y * TS - HLO;

    // ---- load phase: pred + gt extended tiles; accumulate central gt sum ----
    float gtLocal = 0.0f;
    for (int i = tid; i < EXT * EXT; i += NT) {
        int r = i / EXT;
        int c = i - r * EXT;
        int gy = gy0 + r, gx = gx0 + c;
        bool in = ((unsigned)gy < (unsigned)IMG) & ((unsigned)gx < (unsigned)IMG);
        float pv = 0.0f, gv = 0.0f;
        if (in) {
            int off = gy * IMG + gx;
            pv = __ldg(pred + off);
            gv = __ldg(gt + off);
        }
        A0[r * STRIDE + c] = pv;
        Gs[r * STRIDE + c] = gv;
        if (r >= CLO && r < CHI && c >= CLO && c < CHI) gtLocal += gv;
    }
    __syncthreads();

    // ---- thread -> (quad column, row strip) ----
    const int q  = tid / STRIPS;
    const int s  = tid - q * STRIPS;
    const bool active = (q < NQ);
    const int qc = q * 4;
    const int y0 = 1 + s * RPS;
    const int y1 = min(y0 + RPS, EXT - 1);   // rows [y0, y1), global rows 1..136

    float4 cm;   // central-column mask for this quad
    cm.x = (qc + 0 >= CLO && qc + 0 < CHI) ? 1.f : 0.f;
    cm.y = (qc + 1 >= CLO && qc + 1 < CHI) ? 1.f : 0.f;
    cm.z = (qc + 2 >= CLO && qc + 2 < CHI) ? 1.f : 0.f;
    cm.w = (qc + 3 >= CLO && qc + 3 < CHI) ? 1.f : 0.f;

    float fnTotal = 0.0f;
    const float* src = A0;
    float* dst = A1;

    #pragma unroll
    for (int k = 0; k < 5; ++k) {
        const float wk = (float)((k + 1) * (k + 1));
        float iterSum = 0.0f;
        if (active && y0 < y1) {
            float4 cCur, cJunk, hPrev, hCur;
            load_row(src, (y0 - 1) * STRIDE + qc, cJunk, hPrev);
            load_row(src, (y0    ) * STRIDE + qc, cCur,  hCur);
            for (int y = y0; y < y1; ++y) {
                float4 cNext, hNext;
                load_row(src, (y + 1) * STRIDE + qc, cNext, hNext);

                float4 d;
                d.x = __saturatef(hPrev.x + hCur.x + hNext.x);
                d.y = __saturatef(hPrev.y + hCur.y + hNext.y);
                d.z = __saturatef(hPrev.z + hCur.z + hNext.z);
                d.w = __saturatef(hPrev.w + hCur.w + hNext.w);

                float4 sg;
                sg.x = sigm(20.0f * (d.x - cCur.x - 0.5f));
                sg.y = sigm(20.0f * (d.y - cCur.y - 0.5f));
                sg.z = sigm(20.0f * (d.z - cCur.z - 0.5f));
                sg.w = sigm(20.0f * (d.w - cCur.w - 0.5f));

                float4 g4 = *reinterpret_cast<const float4*>(Gs + y * STRIDE + qc);
                float4 fn;
                fn.x = g4.x * sg.x;
                fn.y = g4.y * sg.y;
                fn.z = g4.z * sg.z;
                fn.w = g4.w * sg.w;

                if (k != 4) {   // last iteration's pred update is never read
                    float4 np;
                    np.x = cCur.x + fn.x;
                    np.y = cCur.y + fn.y;
                    np.z = cCur.z + fn.z;
                    np.w = cCur.w + fn.w;
                    *reinterpret_cast<float4*>(dst + y * STRIDE + qc) = np;
                }

                if (y >= CLO && y < CHI)
                    iterSum += fn.x * cm.x + fn.y * cm.y + fn.z * cm.z + fn.w * cm.w;

                hPrev = hCur; hCur = hNext; cCur = cNext;
            }
        }
        fnTotal += wk * iterSum;
        // swap ping-pong
        const float* t = src; src = dst; dst = const_cast<float*>(t);
        __syncthreads();
    }

    // ---- block reduction -> global atomics ----
    for (int o = 16; o; o >>= 1) {
        fnTotal += __shfl_down_sync(0xffffffffu, fnTotal, o);
        gtLocal += __shfl_down_sync(0xffffffffu, gtLocal, o);
    }
    __shared__ float red[NT / 32][2];
    int w = tid >> 5, lane = tid & 31;
    if (lane == 0) { red[w][0] = fnTotal; red[w][1] = gtLocal; }
    __syncthreads();
    if (tid < NT / 32) {
        fnTotal = red[tid][0];
        gtLocal = red[tid][1];
        for (int o = (NT / 64); o; o >>= 1) {
            fnTotal += __shfl_down_sync(0xffffu, fnTotal, o);
            gtLocal += __shfl_down_sync(0xffffu, gtLocal, o);
        }
        if (tid == 0) {
            atomicAdd(&g_acc[0], fnTotal);
            atomicAdd(&g_acc[1], gtLocal);
        }
    }
}

__global__ void wlc_final(float* out) { out[0] = g_acc[0] / g_acc[1]; }

extern "C" void kernel_launch(void* const* d_in, const int* in_sizes, int n_in,
                              void* d_out, int out_size)
{
    const float* pred = (const float*)d_in[0];
    const float* gt   = (const float*)d_in[1];

    const size_t shmem = (size_t)3 * BUF * sizeof(float) + 64;  // 231904 B
    cudaFuncSetAttribute(wlc_main, cudaFuncAttributeMaxDynamicSharedMemorySize,
                         (int)shmem);

    wlc_zero<<<1, 1>>>();
    dim3 grid(IMG / TS, IMG / TS);   // 32 x 32
    wlc_main<<<grid, NT, shmem>>>(pred, gt);
    wlc_final<<<1, 1>>>((float*)d_out);
}

// round 2
// speedup vs baseline: 1.2140x; 1.2140x over previous
#include <cuda_runtime.h>

// WLC loss, fused 5-iteration morphological recurrence, single kernel.
// Tile 128x128, halo 5 -> extended 138x138 in SMEM. Ping-pong pred buffers +
// gt buffer, fp32, ~231.9 KB dynamic SMEM, 1 CTA/SM.
// Thread map: q = tid % 35 (quad column), s = tid / 35 (row strip) so warp
// lanes touch consecutive float4s -> conflict-free LDS/STS.

#define IMG    4096
#define TS     128
#define HLO    5
#define EXT    138            // TS + 2*HLO
#define STRIDE 140            // padded row (floats), 16B-aligned rows
#define BUF    (EXT * STRIDE) // 19320 floats per buffer
#define NT     512
#define NQ     35             // float4 quad-columns covering cols 0..139
#define STRIPS 14
#define RPS    10             // rows per strip (covers rows 1..136)
#define CLO    HLO            // central region [5,133)
#define CHI    (HLO + TS)
#define NBLK   ((IMG / TS) * (IMG / TS))   // 1024

__device__ float    g_acc[2];   // [0]=sum_k w_k*S_k, [1]=gt_sum (zero-init)
__device__ unsigned g_done;     // zero-init; self-resets each launch

__device__ __forceinline__ float ex2f(float x) {
    float y; asm("ex2.approx.f32 %0, %1;" : "=f"(y) : "f"(x)); return y;
}
__device__ __forceinline__ float rcpf(float x) {
    float y; asm("rcp.approx.f32 %0, %1;" : "=f"(y) : "f"(x)); return y;
}
// sigmoid(20*(d - c - 0.5)) = 1 / (1 + 2^(28.8539*(c-d) + 14.42695))
__device__ __forceinline__ float sigm_arg(float c_minus_d) {
    return fmaf(c_minus_d, 28.853900817779268f, 14.426950408889634f);
}

// One row's center float4 + horizontal 3-sums for a quad column.
__device__ __forceinline__ void load_row(const float* __restrict__ S, int idx,
                                         float4& c, float4& h) {
    c = *reinterpret_cast<const float4*>(S + idx);
    float l = S[idx - 1];
    float r = S[idx + 4];
    h.x = l   + c.x + c.y;
    h.y = c.x + c.y + c.z;
    h.z = c.y + c.z + c.w;
    h.w = c.z + c.w + r;
}

__global__ __launch_bounds__(NT, 1)
void wlc_main(const float* __restrict__ pred, const float* __restrict__ gt,
              float* __restrict__ out)
{
    extern __shared__ float sm[];
    float* Gs = sm;               // gt tile
    float* A0 = sm + BUF;         // pred ping
    float* A1 = sm + 2 * BUF;     // pred pong

    const int tid = threadIdx.x;
    const int gx0 = blockIdx.x * TS - HLO;
    const int gy0 = blockIdx.y * TS - HLO;

    // ---- load phase: pred + gt extended tiles; central gt sum ----
    // incremental (r,c): NT = 3*EXT + 98
    float gtLocal = 0.0f;
    {
        int r = tid / EXT;
        int c = tid - r * EXT;
        for (int i = tid; i < EXT * EXT; i += NT) {
            int gy = gy0 + r, gx = gx0 + c;
            bool in = ((unsigned)gy < (unsigned)IMG) & ((unsigned)gx < (unsigned)IMG);
            float pv = 0.0f, gv = 0.0f;
            if (in) {
                int off = gy * IMG + gx;
                pv = __ldg(pred + off);
                gv = __ldg(gt + off);
            }
            A0[r * STRIDE + c] = pv;
            Gs[r * STRIDE + c] = gv;
            if (r >= CLO && r < CHI && c >= CLO && c < CHI) gtLocal += gv;
            c += 98; r += 3;
            if (c >= EXT) { c -= EXT; r += 1; }
        }
    }
    __syncthreads();

    // ---- thread -> (quad column, row strip): lanes get consecutive quads ----
    const int q  = tid % NQ;
    const int s  = tid / NQ;
    const bool active = (s < STRIPS);
    const int qc = q * 4;
    const int y0 = 1 + s * RPS;
    const int y1 = min(y0 + RPS, EXT - 1);   // global rows 1..136

    float4 cm;   // central-column mask for this quad
    cm.x = (qc + 0 >= CLO && qc + 0 < CHI) ? 1.f : 0.f;
    cm.y = (qc + 1 >= CLO && qc + 1 < CHI) ? 1.f : 0.f;
    cm.z = (qc + 2 >= CLO && qc + 2 < CHI) ? 1.f : 0.f;
    cm.w = (qc + 3 >= CLO && qc + 3 < CHI) ? 1.f : 0.f;

    float fnTotal = 0.0f;
    const float* src = A0;
    float* dst = A1;

    #pragma unroll
    for (int k = 0; k < 5; ++k) {
        const float wk = (float)((k + 1) * (k + 1));
        float iterSum = 0.0f;
        if (active) {
            float4 cCur, cJunk, hPrev, hCur;
            load_row(src, (y0 - 1) * STRIDE + qc, cJunk, hPrev);
            load_row(src, (y0    ) * STRIDE + qc, cCur,  hCur);
            #pragma unroll
            for (int rr = 0; rr < RPS; ++rr) {
                const int y = y0 + rr;
                if (y >= y1) break;
                float4 cNext, hNext;
                load_row(src, (y + 1) * STRIDE + qc, cNext, hNext);

                float4 d;
                d.x = __saturatef(hPrev.x + hCur.x + hNext.x);
                d.y = __saturatef(hPrev.y + hCur.y + hNext.y);
                d.z = __saturatef(hPrev.z + hCur.z + hNext.z);
                d.w = __saturatef(hPrev.w + hCur.w + hNext.w);

                float4 sg;
                sg.x = rcpf(1.0f + ex2f(sigm_arg(cCur.x - d.x)));
                sg.y = rcpf(1.0f + ex2f(sigm_arg(cCur.y - d.y)));
                sg.z = rcpf(1.0f + ex2f(sigm_arg(cCur.z - d.z)));
                sg.w = rcpf(1.0f + ex2f(sigm_arg(cCur.w - d.w)));

                float4 g4 = *reinterpret_cast<const float4*>(Gs + y * STRIDE + qc);
                float4 fn;
                fn.x = g4.x * sg.x;
                fn.y = g4.y * sg.y;
                fn.z = g4.z * sg.z;
                fn.w = g4.w * sg.w;

                if (k != 4) {   // last iteration's pred update is never read
                    float4 np;
                    np.x = cCur.x + fn.x;
                    np.y = cCur.y + fn.y;
                    np.z = cCur.z + fn.z;
                    np.w = cCur.w + fn.w;
                    *reinterpret_cast<float4*>(dst + y * STRIDE + qc) = np;
                }

                if (y >= CLO && y < CHI)
                    iterSum += fn.x * cm.x + fn.y * cm.y + fn.z * cm.z + fn.w * cm.w;

                hPrev = hCur; hCur = hNext; cCur = cNext;
            }
        }
        fnTotal += wk * iterSum;
        const float* t = src; src = dst; dst = const_cast<float*>(t);
        __syncthreads();
    }

    // ---- block reduction ----
    #pragma unroll
    for (int o = 16; o; o >>= 1) {
        fnTotal += __shfl_down_sync(0xffffffffu, fnTotal, o);
        gtLocal += __shfl_down_sync(0xffffffffu, gtLocal, o);
    }
    __shared__ float red[NT / 32][2];
    int w = tid >> 5, lane = tid & 31;
    if (lane == 0) { red[w][0] = fnTotal; red[w][1] = gtLocal; }
    __syncthreads();
    if (tid < 32) {
        fnTotal = (tid < NT / 32) ? red[tid][0] : 0.0f;
        gtLocal = (tid < NT / 32) ? red[tid][1] : 0.0f;
        #pragma unroll
        for (int o = 8; o; o >>= 1) {
            fnTotal += __shfl_down_sync(0xffffffffu, fnTotal, o);
            gtLocal += __shfl_down_sync(0xffffffffu, gtLocal, o);
        }
        if (tid == 0) {
            atomicAdd(&g_acc[0], fnTotal);
            atomicAdd(&g_acc[1], gtLocal);
            __threadfence();
            unsigned prev = atomicAdd(&g_done, 1u);
            if (prev == NBLK - 1) {      // last block finalizes + resets
                out[0] = g_acc[0] / g_acc[1];
                g_acc[0] = 0.0f;
                g_acc[1] = 0.0f;
                __threadfence();
                g_done = 0u;
            }
        }
    }
}

extern "C" void kernel_launch(void* const* d_in, const int* in_sizes, int n_in,
                              void* d_out, int out_size)
{
    const float* pred = (const float*)d_in[0];
    const float* gt   = (const float*)d_in[1];

    const size_t shmem = (size_t)3 * BUF * sizeof(float) + 64;  // 231904 B
    cudaFuncSetAttribute(wlc_main, cudaFuncAttributeMaxDynamicSharedMemorySize,
                         (int)shmem);

    dim3 grid(IMG / TS, IMG / TS);   // 32 x 32 = 1024 blocks
    wlc_main<<<grid, NT, shmem>>>(pred, gt, (float*)d_out);
}

// round 3
// speedup vs baseline: 1.6829x; 1.3863x over previous
#include <cuda_runtime.h>

// WLC loss: fused 5-iter morphological recurrence, register-resident pred.
// Warp = full 128-px-wide row band (32 lanes x 4 cols, shfl for horizontal
// neighbors). Thread owns R=7 rows in registers; warp strips exchange 2 edge
// rows/iter via double-buffered smem. gt (pre-halved) in smem. 2 CTAs/SM.

#define IMG    4096
#define NT     512
#define WARPS  16
#define R      7
#define EXTX   128                 // ext tile width (32 lanes * 4)
#define TSX    118                 // useful width
#define EXTY   (WARPS * R + 2)     // 114
#define TSY    (EXTY - 10)         // 104
#define GRIDX  35                  // ceil(4096/118)
#define GRIDY  40                  // ceil(4096/104)
#define NBLK   (GRIDX * GRIDY)     // 1400
#define CLO    5
#define CHIX   123                 // [5,123) useful cols in ext
#define CHIY   (EXTY - 5)          // [5,109) useful rows in ext

// dynamic smem layout (floats)
#define BUFN   (EXTY * EXTX)           // 14592: pred staging, then gt/2
#define ETN    (2 * 17 * EXTX)         // 4352 : top-edge sources  eT[p][w]
#define EBN    (2 * 16 * EXTX)         // 4096 : bottom-edge srcs  eB[p][w]
#define SMEMB  ((BUFN + ETN + EBN) * 4)  // 92160 B

__device__ float    g_acc[2];   // zero-init; self-resets
__device__ unsigned g_done;

__device__ __forceinline__ float tanha(float x) {
    float y; asm("tanh.approx.f32 %0, %1;" : "=f"(y) : "f"(x)); return y;
}

__device__ __forceinline__ float4 ld4(const float* p) {
    return *reinterpret_cast<const float4*>(p);
}
__device__ __forceinline__ void st4(float* p, float4 v) {
    *reinterpret_cast<float4*>(p) = v;
}

// horizontal 3-sums of a register row; neighbors via shfl (boundary lanes
// produce garbage that only lands in the halo-creep zone).
__device__ __forceinline__ float4 hsum(float4 c) {
    float l = __shfl_up_sync(0xffffffffu, c.w, 1);
    float r = __shfl_down_sync(0xffffffffu, c.x, 1);
    float4 h;
    h.x = l   + c.x + c.y;
    h.y = c.x + c.y + c.z;
    h.z = c.y + c.z + c.w;
    h.w = c.z + c.w + r;
    return h;
}

__global__ __launch_bounds__(NT, 2)
void wlc_main(const float* __restrict__ pred, const float* __restrict__ gt,
              float* __restrict__ out)
{
    extern __shared__ float sm[];
    float* buf = sm;                 // staging, then gt/2
    float* eT  = sm + BUFN;          // [2][17][128]
    float* eB  = eT + ETN;           // [2][16][128]

    const int tid = threadIdx.x;
    const int w   = tid >> 5;
    const int l   = tid & 31;
    const int col0 = 4 * l;
    const int gx0 = blockIdx.x * TSX - 5;
    const int gy0 = blockIdx.y * TSY - 5;

    // ---- stage pred into smem (coalesced), bounds -> 0 ----
    for (int i = tid; i < BUFN; i += NT) {
        int r = i >> 7, c = i & 127;
        int gy = gy0 + r, gx = gx0 + c;
        float pv = 0.0f;
        if (((unsigned)gy < (unsigned)IMG) & ((unsigned)gx < (unsigned)IMG))
            pv = __ldg(pred + gy * IMG + gx);
        buf[i] = pv;
    }
    __syncthreads();

    // ---- pick up register strip + initial edges; stage constant edge rows ----
    float4 c[R], cTop, cBot;
    #pragma unroll
    for (int r = 0; r < R; ++r)
        c[r] = ld4(buf + (1 + w * R + r) * EXTX + col0);
    cTop = ld4(buf + (w * R) * EXTX + col0);
    cBot = ld4(buf + (1 + (w + 1) * R) * EXTX + col0);
    if (tid < EXTX) {                       // row 0 -> eT[*][0]
        float v = buf[tid];
        eT[0 * 17 * EXTX + tid] = v;
        eT[1 * 17 * EXTX + tid] = v;
    } else if (tid < 2 * EXTX) {            // row EXTY-1 -> eB[*][15]
        int j = tid - EXTX;
        float v = buf[(EXTY - 1) * EXTX + j];
        eB[(0 * 16 + 15) * EXTX + j] = v;
        eB[(1 * 16 + 15) * EXTX + j] = v;
    }
    __syncthreads();

    // ---- load gt: store gt/2, accumulate central gt sum ----
    float gtLocal = 0.0f;
    for (int i = tid; i < BUFN; i += NT) {
        int r = i >> 7, cc = i & 127;
        int gy = gy0 + r, gx = gx0 + cc;
        float gv = 0.0f;
        if (((unsigned)gy < (unsigned)IMG) & ((unsigned)gx < (unsigned)IMG))
            gv = __ldg(gt + gy * IMG + gx);
        buf[i] = 0.5f * gv;
        if (r >= CLO && r < CHIY && cc >= CLO && cc < CHIX) gtLocal += gv;
    }
    __syncthreads();

    // ---- column mask for the sum ----
    float4 cm;
    cm.x = (col0 + 0 >= CLO && col0 + 0 < CHIX) ? 1.f : 0.f;
    cm.y = (col0 + 1 >= CLO && col0 + 1 < CHIX) ? 1.f : 0.f;
    cm.z = (col0 + 2 >= CLO && col0 + 2 < CHIX) ? 1.f : 0.f;
    cm.w = (col0 + 3 >= CLO && col0 + 3 < CHIX) ? 1.f : 0.f;

    float fnTotal = 0.0f;

    #pragma unroll
    for (int k = 0; k < 5; ++k) {
        const float wk = (float)((k + 1) * (k + 1));
        if (k > 0) {                       // fetch fresh edges, parity (k-1)&1
            int p = (k - 1) & 1;
            cTop = ld4(eT + (p * 17 + w) * EXTX + col0);
            cBot = ld4(eB + (p * 16 + w) * EXTX + col0);
        }
        float4 hP = hsum(cTop);
        float4 cCur = c[0];
        float4 hC = hsum(cCur);
        float iterSum = 0.0f;

        #pragma unroll
        for (int r = 0; r < R; ++r) {
            const int y = 1 + w * R + r;
            float4 cN = (r < R - 1) ? c[r + 1] : cBot;
            float4 hN = hsum(cN);

            float4 d;
            d.x = __saturatef(hP.x + hC.x + hN.x);
            d.y = __saturatef(hP.y + hC.y + hN.y);
            d.z = __saturatef(hP.z + hC.z + hN.z);
            d.w = __saturatef(hP.w + hC.w + hN.w);

            // sigmoid(20(d-p-0.5)) = 0.5 + 0.5*tanh(10(d-p)-5)
            float4 th;
            th.x = tanha(fmaf(d.x - cCur.x, 10.0f, -5.0f));
            th.y = tanha(fmaf(d.y - cCur.y, 10.0f, -5.0f));
            th.z = tanha(fmaf(d.z - cCur.z, 10.0f, -5.0f));
            th.w = tanha(fmaf(d.w - cCur.w, 10.0f, -5.0f));

            float4 g2 = ld4(buf + y * EXTX + col0);   // gt/2
            float4 fn;                                 // fn = g*sigmoid
            fn.x = fmaf(g2.x, th.x, g2.x);
            fn.y = fmaf(g2.y, th.y, g2.y);
            fn.z = fmaf(g2.z, th.z, g2.z);
            fn.w = fmaf(g2.w, th.w, g2.w);

            if (k < 4) {
                float4 np;
                np.x = cCur.x + fn.x;
                np.y = cCur.y + fn.y;
                np.z = cCur.z + fn.z;
                np.w = cCur.w + fn.w;
                c[r] = np;
                int p = k & 1;
                if (r == 0 && w > 0)
                    st4(eB + (p * 16 + (w - 1)) * EXTX + col0, np);  // my first row = (w-1)'s bottom edge
                if (r == R - 1)
                    st4(eT + (p * 17 + (w + 1)) * EXTX + col0, np);  // my last row = (w+1)'s top edge
            }

            if (y >= CLO && y < CHIY) {
                iterSum = fmaf(fn.x, cm.x, iterSum);
                iterSum = fmaf(fn.y, cm.y, iterSum);
                iterSum = fmaf(fn.z, cm.z, iterSum);
                iterSum = fmaf(fn.w, cm.w, iterSum);
            }

            hP = hC; hC = hN; cCur = cN;
        }
        fnTotal += wk * iterSum;
        if (k < 4) __syncthreads();
    }

    // ---- block reduction -> global atomics ----
    #pragma unroll
    for (int o = 16; o; o >>= 1) {
        fnTotal += __shfl_down_sync(0xffffffffu, fnTotal, o);
        gtLocal += __shfl_down_sync(0xffffffffu, gtLocal, o);
    }
    __shared__ float red[WARPS][2];
    if (l == 0) { red[w][0] = fnTotal; red[w][1] = gtLocal; }
    __syncthreads();
    if (tid < 32) {
        fnTotal = (tid < WARPS) ? red[tid][0] : 0.0f;
        gtLocal = (tid < WARPS) ? red[tid][1] : 0.0f;
        #pragma unroll
        for (int o = 8; o; o >>= 1) {
            fnTotal += __shfl_down_sync(0xffffffffu, fnTotal, o);
            gtLocal += __shfl_down_sync(0xffffffffu, gtLocal, o);
        }
        if (tid == 0) {
            atomicAdd(&g_acc[0], fnTotal);
            atomicAdd(&g_acc[1], gtLocal);
            __threadfence();
            unsigned prev = atomicAdd(&g_done, 1u);
            if (prev == NBLK - 1) {
                out[0] = g_acc[0] / g_acc[1];
                g_acc[0] = 0.0f;
                g_acc[1] = 0.0f;
                __threadfence();
                g_done = 0u;
            }
        }
    }
}

extern "C" void kernel_launch(void* const* d_in, const int* in_sizes, int n_in,
                              void* d_out, int out_size)
{
    const float* pred = (const float*)d_in[0];
    const float* gt   = (const float*)d_in[1];

    cudaFuncSetAttribute(wlc_main, cudaFuncAttributeMaxDynamicSharedMemorySize,
                         SMEMB);

    dim3 grid(GRIDX, GRIDY);       // 35 x 40 = 1400 blocks
    wlc_main<<<grid, NT, SMEMB>>>(pred, gt, (float*)d_out);
}